// round 7
// baseline (speedup 1.0000x reference)
#include <cuda_runtime.h>
#include <cuda_bf16.h>

#define NUSERS 100000
#define NITEMS 50000
#define DIM 64
#define NNODES 150001            // users + items + padding row
#define ND 9600064               // NNODES * DIM
#define NEDGES 4800000

#define SCAN_CHUNK 512
#define NB_SCAN ((NNODES + SCAN_CHUNK - 1) / SCAN_CHUNK)   // 293
#define NZERO4 ((NNODES + 3) / 4)                           // 37501 int4 stores

// ---------------- device scratch (static allocation — allowed) -------------
__device__ int   g_idx_stride;            // 2 if int64 indices, 1 if int32
__device__ int   g_counts[NNODES + 15];   // row degrees
__device__ int   g_rowptr[NNODES];        // row start slots (non-monotonic ok)
__device__ int   g_cursor[NNODES];        // scatter cursors
__device__ int   g_total;                 // block-base reservation counter
__device__ int   g_rows32[NEDGES];        // compacted int32 row ids
__device__ int   g_cols32[NEDGES];        // compacted int32 col ids
__device__ int2  g_edges[NEDGES];         // packed CSR records: col, bits(val)

// ---------------------------------------------------------------------------
// Launch 0: zero counters + total + (thread 0) detect index width.
// int64 LE values < 2^31 have zero high words; 32 zero checks => certain.
// ---------------------------------------------------------------------------
__global__ void gcn_zero_detect(const int* __restrict__ rows32,
                                const int* __restrict__ cols32) {
    int i = blockIdx.x * blockDim.x + threadIdx.x;
    if (i < NZERO4)
        reinterpret_cast<int4*>(g_counts)[i] = make_int4(0, 0, 0, 0);
    if (i == 0) {
        g_total = 0;
        bool is64 = true;
        #pragma unroll
        for (int k = 0; k < 16; k++) {
            if (rows32[2 * k + 1] != 0) is64 = false;
            if (cols32[2 * k + 1] != 0) is64 = false;
        }
        g_idx_stride = is64 ? 2 : 1;
    }
}

// ---------------------------------------------------------------------------
// Launch 1: histogram of row degrees + compact both index arrays to int32.
// Single streaming pass over the wide (possibly int64) inputs; scatter then
// re-reads only the 38.4MB compact arrays (L2-hot).
// ---------------------------------------------------------------------------
__global__ void gcn_hist_kernel(const int* __restrict__ rowsw,
                                const int* __restrict__ colsw) {
    int e = blockIdx.x * blockDim.x + threadIdx.x;
    if (e < NEDGES) {
        int stride = g_idx_stride;
        int r = rowsw[e * stride];
        int c = colsw[e * stride];
        g_rows32[e] = r;
        g_cols32[e] = c;
        atomicAdd(&g_counts[r], 1);              // no return use -> RED
    }
}

// ---------------------------------------------------------------------------
// Launch 2: single-kernel "scan": per-block smem exclusive scan + atomic
// block-base reservation. Row starts are contiguous per row but blocks land
// in arbitrary order — SpMM uses (start, count), never start monotonicity.
// ---------------------------------------------------------------------------
__global__ void gcn_scan_fused(void) {
    __shared__ int s[SCAN_CHUNK];
    __shared__ int base_sh;
    int t = threadIdx.x;
    int i = blockIdx.x * SCAN_CHUNK + t;
    int x = (i < NNODES) ? g_counts[i] : 0;
    s[t] = x;
    __syncthreads();
    // inclusive Hillis-Steele
    for (int off = 1; off < SCAN_CHUNK; off <<= 1) {
        int v = (t >= off) ? s[t - off] : 0;
        __syncthreads();
        s[t] += v;
        __syncthreads();
    }
    if (t == SCAN_CHUNK - 1)
        base_sh = atomicAdd(&g_total, s[SCAN_CHUNK - 1]);
    __syncthreads();
    if (i < NNODES) {
        int start = base_sh + s[t] - x;          // exclusive within block
        g_rowptr[i] = start;
        g_cursor[i] = start;
    }
}

// ---------------------------------------------------------------------------
// Launch 3: scatter edges into packed CSR slots (compact int32 sources).
// ---------------------------------------------------------------------------
__global__ void gcn_scatter_kernel(const float* __restrict__ vals) {
    int e = blockIdx.x * blockDim.x + threadIdx.x;
    if (e < NEDGES) {
        int r = g_rows32[e];
        int c = g_cols32[e];
        float v = vals[e];
        int pos = atomicAdd(&g_cursor[r], 1);
        g_edges[pos] = make_int2(c, __float_as_int(v));
    }
}

// ---------------------------------------------------------------------------
// Launch 4: ego = concat(user_emb, item_emb). h1..h3 fully overwritten later.
// ---------------------------------------------------------------------------
__global__ void gcn_init_kernel(const float4* __restrict__ user_emb,
                                const float4* __restrict__ item_emb,
                                float4* __restrict__ ego) {
    const int n4 = ND / 4;
    const int u4 = NUSERS * (DIM / 4);
    int i = blockIdx.x * blockDim.x + threadIdx.x;
    if (i < n4)
        ego[i] = (i < u4) ? user_emb[i] : item_emb[i - u4];
}

// ---------------------------------------------------------------------------
// Launches 5-7 (ncu samples #5 = first SpMM): CSR SpMM, warp per node,
// float2 per lane, 4-wide unrolled gather (front-batched for MLP).
// FUSE variant also emits hsum = ego + h1 + h2 + h3.
// ---------------------------------------------------------------------------
template <bool FUSE>
__global__ void __launch_bounds__(256)
gcn_csr_spmm(const float* __restrict__ h,
             float* __restrict__ y,
             const float* __restrict__ ego,
             const float* __restrict__ h1,
             const float* __restrict__ h2,
             float* __restrict__ hsum) {
    int warp = (blockIdx.x * blockDim.x + threadIdx.x) >> 5;
    if (warp >= NNODES) return;
    int lane = threadIdx.x & 31;
    int off = lane * 2;

    int start = __ldg(&g_rowptr[warp]);
    int end   = start + __ldg(&g_counts[warp]);

    float ax = 0.f, ay = 0.f;
    int i = start;
    for (; i + 4 <= end; i += 4) {
        int2 e0 = g_edges[i];
        int2 e1 = g_edges[i + 1];
        int2 e2 = g_edges[i + 2];
        int2 e3 = g_edges[i + 3];
        float2 g0 = *reinterpret_cast<const float2*>(h + (size_t)e0.x * DIM + off);
        float2 g1 = *reinterpret_cast<const float2*>(h + (size_t)e1.x * DIM + off);
        float2 g2 = *reinterpret_cast<const float2*>(h + (size_t)e2.x * DIM + off);
        float2 g3 = *reinterpret_cast<const float2*>(h + (size_t)e3.x * DIM + off);
        float v0 = __int_as_float(e0.y), v1 = __int_as_float(e1.y);
        float v2 = __int_as_float(e2.y), v3 = __int_as_float(e3.y);
        ax += v0 * g0.x + v1 * g1.x + v2 * g2.x + v3 * g3.x;
        ay += v0 * g0.y + v1 * g1.y + v2 * g2.y + v3 * g3.y;
    }
    for (; i < end; i++) {
        int2 e0 = g_edges[i];
        float2 g0 = *reinterpret_cast<const float2*>(h + (size_t)e0.x * DIM + off);
        float v0 = __int_as_float(e0.y);
        ax += v0 * g0.x;
        ay += v0 * g0.y;
    }

    size_t base = (size_t)warp * DIM + off;
    *reinterpret_cast<float2*>(y + base) = make_float2(ax, ay);

    if (FUSE) {
        float2 a = *reinterpret_cast<const float2*>(ego + base);
        float2 b = *reinterpret_cast<const float2*>(h1 + base);
        float2 c = *reinterpret_cast<const float2*>(h2 + base);
        *reinterpret_cast<float2*>(hsum + base) =
            make_float2(a.x + b.x + c.x + ax, a.y + b.y + c.y + ay);
    }
}

// ---------------------------------------------------------------------------
// kernel_launch — graph-capturable, allocation-free.
// Output layout (out_size = 5*ND): [h_sum | ego | h1 | h2 | h3]
// ---------------------------------------------------------------------------
extern "C" void kernel_launch(void* const* d_in, const int* in_sizes, int n_in,
                              void* d_out, int out_size) {
    const float* user_emb = (const float*)d_in[0];
    const float* item_emb = (const float*)d_in[1];
    const float* vals     = (const float*)d_in[2];
    const int*   rowsw    = (const int*)d_in[3];
    const int*   colsw    = (const int*)d_in[4];

    float* out  = (float*)d_out;
    float* hsum = out;
    float* ego  = out + (size_t)ND;
    float* h1   = out + (size_t)2 * ND;
    float* h2   = out + (size_t)3 * ND;
    float* h3   = out + (size_t)4 * ND;

    // 0
    gcn_zero_detect<<<(NZERO4 + 255) / 256, 256>>>(rowsw, colsw);
    // 1
    gcn_hist_kernel<<<(NEDGES + 255) / 256, 256>>>(rowsw, colsw);
    // 2
    gcn_scan_fused<<<NB_SCAN, SCAN_CHUNK>>>();
    // 3
    gcn_scatter_kernel<<<(NEDGES + 255) / 256, 256>>>(vals);
    // 4
    {
        const int n4 = ND / 4;
        gcn_init_kernel<<<(n4 + 255) / 256, 256>>>(
            (const float4*)user_emb, (const float4*)item_emb, (float4*)ego);
    }
    // 5-7
    {
        long long threads = (long long)NNODES * 32;
        unsigned grd = (unsigned)((threads + 255) / 256);
        gcn_csr_spmm<false><<<grd, 256>>>(ego, h1, nullptr, nullptr, nullptr,
                                          nullptr);
        gcn_csr_spmm<false><<<grd, 256>>>(h1, h2, nullptr, nullptr, nullptr,
                                          nullptr);
        gcn_csr_spmm<true><<<grd, 256>>>(h2, h3, ego, h1, h2, hsum);
    }
}

// round 8
// speedup vs baseline: 1.0152x; 1.0152x over previous
#include <cuda_runtime.h>
#include <cuda_bf16.h>

#define NUSERS 100000
#define NITEMS 50000
#define DIM 64
#define NNODES 150001            // users + items + padding row
#define ND 9600064               // NNODES * DIM
#define NEDGES 4800000

#define SCAN_CHUNK 512
#define NB_SCAN ((NNODES + SCAN_CHUNK - 1) / SCAN_CHUNK)   // 293
#define NZERO4 ((NNODES + 3) / 4)                           // 37501 int4 stores
#define EDGE_BATCH 4
#define NEB (NEDGES / EDGE_BATCH)                           // 1,200,000 threads

// ---------------- device scratch (static allocation — allowed) -------------
__device__ int   g_idx_stride;            // 2 if int64 indices, 1 if int32
__device__ int   g_counts[NNODES + 15];   // row degrees
__device__ int   g_rowptr[NNODES];        // row start slots (non-monotonic ok)
__device__ int   g_cursor[NNODES];        // scatter cursors
__device__ int   g_total;                 // block-base reservation counter
__device__ int2  g_edges[NEDGES];         // packed CSR records: col, bits(val)

// ---------------------------------------------------------------------------
// Launch 0: zero counters + total + (thread 0) detect index width.
// int64 LE values < 2^31 have zero high words; 32 zero checks => certain.
// ---------------------------------------------------------------------------
__global__ void gcn_zero_detect(const int* __restrict__ rows32,
                                const int* __restrict__ cols32) {
    int i = blockIdx.x * blockDim.x + threadIdx.x;
    if (i < NZERO4)
        reinterpret_cast<int4*>(g_counts)[i] = make_int4(0, 0, 0, 0);
    if (i == 0) {
        g_total = 0;
        bool is64 = true;
        #pragma unroll
        for (int k = 0; k < 16; k++) {
            if (rows32[2 * k + 1] != 0) is64 = false;
            if (cols32[2 * k + 1] != 0) is64 = false;
        }
        g_idx_stride = is64 ? 2 : 1;
    }
}

// ---------------------------------------------------------------------------
// Launch 1: histogram of row degrees. 4 edges/thread -> 4 independent REDs
// in flight (latency hiding on the atomic pipe).
// ---------------------------------------------------------------------------
__global__ void gcn_hist_kernel(const int* __restrict__ rowsw) {
    int t = blockIdx.x * blockDim.x + threadIdx.x;
    if (t >= NEB) return;
    int e = t * EDGE_BATCH;
    int stride = g_idx_stride;
    int r0 = rowsw[(e + 0) * stride];
    int r1 = rowsw[(e + 1) * stride];
    int r2 = rowsw[(e + 2) * stride];
    int r3 = rowsw[(e + 3) * stride];
    atomicAdd(&g_counts[r0], 1);             // no return use -> RED
    atomicAdd(&g_counts[r1], 1);
    atomicAdd(&g_counts[r2], 1);
    atomicAdd(&g_counts[r3], 1);
}

// ---------------------------------------------------------------------------
// Launch 2: fused scan: per-block smem inclusive scan + atomic block-base
// reservation. Starts are contiguous per row; SpMM uses (start, count) only.
// ---------------------------------------------------------------------------
__global__ void gcn_scan_fused(void) {
    __shared__ int s[SCAN_CHUNK];
    __shared__ int base_sh;
    int t = threadIdx.x;
    int i = blockIdx.x * SCAN_CHUNK + t;
    int x = (i < NNODES) ? g_counts[i] : 0;
    s[t] = x;
    __syncthreads();
    for (int off = 1; off < SCAN_CHUNK; off <<= 1) {
        int v = (t >= off) ? s[t - off] : 0;
        __syncthreads();
        s[t] += v;
        __syncthreads();
    }
    if (t == SCAN_CHUNK - 1)
        base_sh = atomicAdd(&g_total, s[SCAN_CHUNK - 1]);
    __syncthreads();
    if (i < NNODES) {
        int start = base_sh + s[t] - x;          // exclusive within block
        g_rowptr[i] = start;
        g_cursor[i] = start;
    }
}

// ---------------------------------------------------------------------------
// Launch 3: scatter edges into packed CSR slots. 4 edges/thread -> 4
// independent ATOMG reservations + 4 stores overlap (was the latency
// bottleneck at 1 edge/thread: issue=4.9%).
// ---------------------------------------------------------------------------
__global__ void gcn_scatter_kernel(const int* __restrict__ rowsw,
                                   const int* __restrict__ colsw,
                                   const float* __restrict__ vals) {
    int t = blockIdx.x * blockDim.x + threadIdx.x;
    if (t >= NEB) return;
    int e = t * EDGE_BATCH;
    int stride = g_idx_stride;

    int r0 = rowsw[(e + 0) * stride];
    int r1 = rowsw[(e + 1) * stride];
    int r2 = rowsw[(e + 2) * stride];
    int r3 = rowsw[(e + 3) * stride];
    int c0 = colsw[(e + 0) * stride];
    int c1 = colsw[(e + 1) * stride];
    int c2 = colsw[(e + 2) * stride];
    int c3 = colsw[(e + 3) * stride];
    float4 v = *reinterpret_cast<const float4*>(vals + e);

    int p0 = atomicAdd(&g_cursor[r0], 1);
    int p1 = atomicAdd(&g_cursor[r1], 1);
    int p2 = atomicAdd(&g_cursor[r2], 1);
    int p3 = atomicAdd(&g_cursor[r3], 1);

    g_edges[p0] = make_int2(c0, __float_as_int(v.x));
    g_edges[p1] = make_int2(c1, __float_as_int(v.y));
    g_edges[p2] = make_int2(c2, __float_as_int(v.z));
    g_edges[p3] = make_int2(c3, __float_as_int(v.w));
}

// ---------------------------------------------------------------------------
// Launch 4: ego = concat(user_emb, item_emb). h1..h3 fully overwritten later.
// ---------------------------------------------------------------------------
__global__ void gcn_init_kernel(const float4* __restrict__ user_emb,
                                const float4* __restrict__ item_emb,
                                float4* __restrict__ ego) {
    const int n4 = ND / 4;
    const int u4 = NUSERS * (DIM / 4);
    int i = blockIdx.x * blockDim.x + threadIdx.x;
    if (i < n4)
        ego[i] = (i < u4) ? user_emb[i] : item_emb[i - u4];
}

// ---------------------------------------------------------------------------
// Launches 5-7: CSR SpMM, warp per node, float2 per lane, 4-wide unrolled
// gather (front-batched for MLP). FUSE variant also emits
// hsum = ego + h1 + h2 + h3.
// ---------------------------------------------------------------------------
template <bool FUSE>
__global__ void __launch_bounds__(256)
gcn_csr_spmm(const float* __restrict__ h,
             float* __restrict__ y,
             const float* __restrict__ ego,
             const float* __restrict__ h1,
             const float* __restrict__ h2,
             float* __restrict__ hsum) {
    int warp = (blockIdx.x * blockDim.x + threadIdx.x) >> 5;
    if (warp >= NNODES) return;
    int lane = threadIdx.x & 31;
    int off = lane * 2;

    int start = __ldg(&g_rowptr[warp]);
    int end   = start + __ldg(&g_counts[warp]);

    float ax = 0.f, ay = 0.f;
    int i = start;
    for (; i + 4 <= end; i += 4) {
        int2 e0 = g_edges[i];
        int2 e1 = g_edges[i + 1];
        int2 e2 = g_edges[i + 2];
        int2 e3 = g_edges[i + 3];
        float2 g0 = *reinterpret_cast<const float2*>(h + (size_t)e0.x * DIM + off);
        float2 g1 = *reinterpret_cast<const float2*>(h + (size_t)e1.x * DIM + off);
        float2 g2 = *reinterpret_cast<const float2*>(h + (size_t)e2.x * DIM + off);
        float2 g3 = *reinterpret_cast<const float2*>(h + (size_t)e3.x * DIM + off);
        float v0 = __int_as_float(e0.y), v1 = __int_as_float(e1.y);
        float v2 = __int_as_float(e2.y), v3 = __int_as_float(e3.y);
        ax += v0 * g0.x + v1 * g1.x + v2 * g2.x + v3 * g3.x;
        ay += v0 * g0.y + v1 * g1.y + v2 * g2.y + v3 * g3.y;
    }
    for (; i < end; i++) {
        int2 e0 = g_edges[i];
        float2 g0 = *reinterpret_cast<const float2*>(h + (size_t)e0.x * DIM + off);
        float v0 = __int_as_float(e0.y);
        ax += v0 * g0.x;
        ay += v0 * g0.y;
    }

    size_t base = (size_t)warp * DIM + off;
    *reinterpret_cast<float2*>(y + base) = make_float2(ax, ay);

    if (FUSE) {
        float2 a = *reinterpret_cast<const float2*>(ego + base);
        float2 b = *reinterpret_cast<const float2*>(h1 + base);
        float2 c = *reinterpret_cast<const float2*>(h2 + base);
        *reinterpret_cast<float2*>(hsum + base) =
            make_float2(a.x + b.x + c.x + ax, a.y + b.y + c.y + ay);
    }
}

// ---------------------------------------------------------------------------
// kernel_launch — graph-capturable, allocation-free.
// Output layout (out_size = 5*ND): [h_sum | ego | h1 | h2 | h3]
// ---------------------------------------------------------------------------
extern "C" void kernel_launch(void* const* d_in, const int* in_sizes, int n_in,
                              void* d_out, int out_size) {
    const float* user_emb = (const float*)d_in[0];
    const float* item_emb = (const float*)d_in[1];
    const float* vals     = (const float*)d_in[2];
    const int*   rowsw    = (const int*)d_in[3];
    const int*   colsw    = (const int*)d_in[4];

    float* out  = (float*)d_out;
    float* hsum = out;
    float* ego  = out + (size_t)ND;
    float* h1   = out + (size_t)2 * ND;
    float* h2   = out + (size_t)3 * ND;
    float* h3   = out + (size_t)4 * ND;

    // 0
    gcn_zero_detect<<<(NZERO4 + 255) / 256, 256>>>(rowsw, colsw);
    // 1
    gcn_hist_kernel<<<(NEB + 255) / 256, 256>>>(rowsw);
    // 2
    gcn_scan_fused<<<NB_SCAN, SCAN_CHUNK>>>();
    // 3
    gcn_scatter_kernel<<<(NEB + 255) / 256, 256>>>(rowsw, colsw, vals);
    // 4
    {
        const int n4 = ND / 4;
        gcn_init_kernel<<<(n4 + 255) / 256, 256>>>(
            (const float4*)user_emb, (const float4*)item_emb, (float4*)ego);
    }
    // 5-7
    {
        long long threads = (long long)NNODES * 32;
        unsigned grd = (unsigned)((threads + 255) / 256);
        gcn_csr_spmm<false><<<grd, 256>>>(ego, h1, nullptr, nullptr, nullptr,
                                          nullptr);
        gcn_csr_spmm<false><<<grd, 256>>>(h1, h2, nullptr, nullptr, nullptr,
                                          nullptr);
        gcn_csr_spmm<true><<<grd, 256>>>(h2, h3, ego, h1, h2, hsum);
    }
}